// round 11
// baseline (speedup 1.0000x reference)
#include <cuda_runtime.h>
#include <math.h>

#define FDIM 512
#define NOUT 10
#define SPW  16           // samples per warp
#define WPB  4            // warps per block
#define PI_F 3.14159265358979323846f

__device__ __forceinline__ float dot4(float4 a, float4 b) {
    return a.x*b.x + a.y*b.y + a.z*b.z + a.w*b.w;
}
__device__ __forceinline__ float fast_tanh(float x) {
    float y;
    asm("tanh.approx.f32 %0, %1;" : "=f"(y) : "f"(x));
    return y;
}

// ---------------------------------------------------------------------------
// Fused kernel: GEMV (weights in registers) -> per-warp shared staging ->
// per-lane 3-qubit sim epilogue (lanes 0..15, SPW=16).
// ---------------------------------------------------------------------------
__global__ __launch_bounds__(128, 5)
void qnet_fused_kernel(const float* __restrict__ x,        // (B,512)
                       const float* __restrict__ pre_W,    // (3,512)
                       const float* __restrict__ pre_b,    // (3,)
                       const float* __restrict__ q_params, // (45,), rows 1..2 used
                       const float* __restrict__ post_W,   // (10,3)
                       const float* __restrict__ post_b,   // (10,)
                       float* __restrict__ out,            // (B,10)
                       int B)
{
    __shared__ float s_md[WPB][SPW][3];                 // staged dots
    __shared__ float s_tc[6], s_ts[6], s_pb[3], s_pw[30], s_pbo[10];

    if (threadIdx.x < 6) {                 // parallel trig preamble (MUFU)
        float th = 0.5f * q_params[3 + threadIdx.x];
        s_ts[threadIdx.x] = __sinf(th);
        s_tc[threadIdx.x] = __cosf(th);
    }
    if (threadIdx.x < 3)  s_pb[threadIdx.x]  = pre_b[threadIdx.x];
    if (threadIdx.x < 30) s_pw[threadIdx.x]  = post_W[threadIdx.x];
    if (threadIdx.x < 10) s_pbo[threadIdx.x] = post_b[threadIdx.x];

    const int lane = threadIdx.x & 31;
    const int wib  = threadIdx.x >> 5;
    const int warp = blockIdx.x * WPB + wib;
    const int base = warp * SPW;
    if (base >= B) return;

    // Each lane owns float4 chunks {32i + lane}, i=0..3, of each weight row.
    float4 wa[4], wb[4], wc[4];
    #pragma unroll
    for (int i = 0; i < 4; i++) {
        wa[i] = ((const float4*)(pre_W           ))[i * 32 + lane];
        wb[i] = ((const float4*)(pre_W +     FDIM))[i * 32 + lane];
        wc[i] = ((const float4*)(pre_W + 2 * FDIM))[i * 32 + lane];
    }

    // ---------------- Phase A: 16 rows, 2 per iteration (MLP=8) ---------------
    #pragma unroll 1
    for (int j = 0; j < SPW / 2; j++) {
        int r0 = base + 2 * j;
        int r1 = r0 + 1;
        if (r0 >= B) r0 = B - 1;
        if (r1 >= B) r1 = B - 1;
        const float4* xp0 = (const float4*)(x + (size_t)r0 * FDIM);
        const float4* xp1 = (const float4*)(x + (size_t)r1 * FDIM);

        float4 v[8];
        #pragma unroll
        for (int i = 0; i < 4; i++) {
            v[i]     = __ldcs(&xp0[i * 32 + lane]);
            v[i + 4] = __ldcs(&xp1[i * 32 + lane]);
        }

        float a0 = 0.f, b0 = 0.f, c0 = 0.f;
        float a1 = 0.f, b1 = 0.f, c1 = 0.f;
        #pragma unroll
        for (int i = 0; i < 4; i++) {
            a0 += dot4(v[i],     wa[i]);
            b0 += dot4(v[i],     wb[i]);
            c0 += dot4(v[i],     wc[i]);
            a1 += dot4(v[i + 4], wa[i]);
            b1 += dot4(v[i + 4], wb[i]);
            c1 += dot4(v[i + 4], wc[i]);
        }

        #pragma unroll
        for (int off = 16; off; off >>= 1) {
            a0 += __shfl_xor_sync(0xffffffffu, a0, off);
            b0 += __shfl_xor_sync(0xffffffffu, b0, off);
            c0 += __shfl_xor_sync(0xffffffffu, c0, off);
            a1 += __shfl_xor_sync(0xffffffffu, a1, off);
            b1 += __shfl_xor_sync(0xffffffffu, b1, off);
            c1 += __shfl_xor_sync(0xffffffffu, c1, off);
        }

        if (lane < 3) {
            float o0 = (lane == 0) ? a0 : (lane == 1) ? b0 : c0;
            float o1 = (lane == 0) ? a1 : (lane == 1) ? b1 : c1;
            s_md[wib][2 * j    ][lane] = o0;
            s_md[wib][2 * j + 1][lane] = o1;
        }
    }
    __syncwarp();

    // ---------------- Phase B: one sample per lane (lanes 0..15) --------------
    if (lane >= SPW) return;
    int row = base + lane;
    if (row >= B) return;

    float h0 = fast_tanh(s_md[wib][lane][0] + s_pb[0]) * (PI_F * 0.25f);
    float h1 = fast_tanh(s_md[wib][lane][1] + s_pb[1]) * (PI_F * 0.25f);
    float h2 = fast_tanh(s_md[wib][lane][2] + s_pb[2]) * (PI_F * 0.25f);

    float st[8];
    const float inv8 = 0.3535533905932738f;    // amplitudes after H layer
    #pragma unroll
    for (int i = 0; i < 8; i++) st[i] = inv8;

    float ec, es;
    es = __sinf(h0); ec = __cosf(h0);          // encoding RY qubit 0 (stride 4)
    #pragma unroll
    for (int i = 0; i < 4; i++) {
        float a0 = st[i], a1 = st[i + 4];
        st[i]     = ec * a0 - es * a1;
        st[i + 4] = es * a0 + ec * a1;
    }
    es = __sinf(h1); ec = __cosf(h1);          // qubit 1 (stride 2)
    #pragma unroll
    for (int g = 0; g < 2; g++)
        #pragma unroll
        for (int i = 0; i < 2; i++) {
            int i0 = g * 4 + i;
            float a0 = st[i0], a1 = st[i0 + 2];
            st[i0]     = ec * a0 - es * a1;
            st[i0 + 2] = es * a0 + ec * a1;
        }
    es = __sinf(h2); ec = __cosf(h2);          // qubit 2 (stride 1)
    #pragma unroll
    for (int i0 = 0; i0 < 8; i0 += 2) {
        float a0 = st[i0], a1 = st[i0 + 1];
        st[i0]     = ec * a0 - es * a1;
        st[i0 + 1] = es * a0 + ec * a1;
    }

    #pragma unroll
    for (int k = 0; k < 2; k++) {
        float t;
        // CNOT01: swap (4,6),(5,7); CNOT12: swap (2,3),(6,7)
        t = st[4]; st[4] = st[6]; st[6] = t;
        t = st[5]; st[5] = st[7]; st[7] = t;
        t = st[2]; st[2] = st[3]; st[3] = t;
        t = st[6]; st[6] = st[7]; st[7] = t;

        float c0 = s_tc[k * 3 + 0], sg0 = s_ts[k * 3 + 0];
        float c1 = s_tc[k * 3 + 1], sg1 = s_ts[k * 3 + 1];
        float c2 = s_tc[k * 3 + 2], sg2 = s_ts[k * 3 + 2];
        #pragma unroll
        for (int i = 0; i < 4; i++) {
            float a0 = st[i], a1 = st[i + 4];
            st[i]     = c0 * a0 - sg0 * a1;
            st[i + 4] = sg0 * a0 + c0 * a1;
        }
        #pragma unroll
        for (int g = 0; g < 2; g++)
            #pragma unroll
            for (int i = 0; i < 2; i++) {
                int i0 = g * 4 + i;
                float a0 = st[i0], a1 = st[i0 + 2];
                st[i0]     = c1 * a0 - sg1 * a1;
                st[i0 + 2] = sg1 * a0 + c1 * a1;
            }
        #pragma unroll
        for (int i0 = 0; i0 < 8; i0 += 2) {
            float a0 = st[i0], a1 = st[i0 + 1];
            st[i0]     = c2 * a0 - sg2 * a1;
            st[i0 + 1] = sg2 * a0 + c2 * a1;
        }
    }

    float p[8];
    #pragma unroll
    for (int i = 0; i < 8; i++) p[i] = st[i] * st[i];
    float z0 = (p[0] + p[1] + p[2] + p[3]) - (p[4] + p[5] + p[6] + p[7]);
    float z1 = (p[0] + p[1] + p[4] + p[5]) - (p[2] + p[3] + p[6] + p[7]);
    float z2 = (p[0] + p[2] + p[4] + p[6]) - (p[1] + p[3] + p[5] + p[7]);

    float2* op = (float2*)(out + (size_t)row * NOUT);
    #pragma unroll
    for (int k = 0; k < 5; k++) {
        float2 w;
        w.x = z0 * s_pw[(2*k)   * 3 + 0] + z1 * s_pw[(2*k)   * 3 + 1]
            + z2 * s_pw[(2*k)   * 3 + 2] + s_pbo[2*k];
        w.y = z0 * s_pw[(2*k+1) * 3 + 0] + z1 * s_pw[(2*k+1) * 3 + 1]
            + z2 * s_pw[(2*k+1) * 3 + 2] + s_pbo[2*k+1];
        op[k] = w;
    }
}

extern "C" void kernel_launch(void* const* d_in, const int* in_sizes, int n_in,
                              void* d_out, int out_size) {
    const float* x      = (const float*)d_in[0];
    const float* pre_W  = (const float*)d_in[1];
    const float* pre_b  = (const float*)d_in[2];
    const float* q_par  = (const float*)d_in[3];
    const float* post_W = (const float*)d_in[4];
    const float* post_b = (const float*)d_in[5];
    float* out = (float*)d_out;

    int B = in_sizes[0] / FDIM;

    int warps_needed = (B + SPW - 1) / SPW;              // 4096 for B=65536
    int blocks       = (warps_needed + WPB - 1) / WPB;   // 1024 blocks of 128
    qnet_fused_kernel<<<blocks, 128>>>(x, pre_W, pre_b, q_par,
                                       post_W, post_b, out, B);
}

// round 12
// speedup vs baseline: 1.0724x; 1.0724x over previous
#include <cuda_runtime.h>
#include <math.h>

#define FDIM  512
#define NOUT  10
#define SPW   32          // samples (rows) per warp
#define WPB   4           // warps per block
#define DEPTH 4           // cp.async pipeline stages (rows) per warp
#define ROWB  2048        // bytes per row
#define PI_F  3.14159265358979323846f

__device__ __forceinline__ float dot4(float4 a, float4 b) {
    return a.x*b.x + a.y*b.y + a.z*b.z + a.w*b.w;
}
__device__ __forceinline__ float fast_tanh(float x) {
    float y;
    asm("tanh.approx.f32 %0, %1;" : "=f"(y) : "f"(x));
    return y;
}
__device__ __forceinline__ unsigned smem_u32(const void* p) {
    unsigned a;
    asm("{ .reg .u64 t; cvta.to.shared.u64 t, %1; cvt.u32.u64 %0, t; }"
        : "=r"(a) : "l"(p));
    return a;
}
// Copy one 2KB row gmem->smem: each lane moves 4x16B.
__device__ __forceinline__ void cp_row(unsigned dst, const float* src, int lane) {
    #pragma unroll
    for (int p = 0; p < 4; p++) {
        asm volatile("cp.async.cg.shared.global [%0], [%1], 16;"
                     :: "r"(dst + lane * 16 + p * 512),
                        "l"(src + lane * 4 + p * 128) : "memory");
    }
}

// ---------------------------------------------------------------------------
// Fused: cp.async-pipelined GEMV (weights in regs, x staged via smem ring)
// -> per-warp staged dots -> per-lane 3-qubit sim epilogue (32 samples/warp).
// ---------------------------------------------------------------------------
__global__ __launch_bounds__(128, 5)
void qnet_fused_kernel(const float* __restrict__ x,        // (B,512)
                       const float* __restrict__ pre_W,    // (3,512)
                       const float* __restrict__ pre_b,    // (3,)
                       const float* __restrict__ q_params, // (45,), rows 1..2 used
                       const float* __restrict__ post_W,   // (10,3)
                       const float* __restrict__ post_b,   // (10,)
                       float* __restrict__ out,            // (B,10)
                       int B)
{
    __shared__ float s_x[WPB][DEPTH][FDIM];             // 32 KB ring buffers
    __shared__ float s_md[WPB][SPW][3];                 // staged dots
    __shared__ float s_tc[6], s_ts[6], s_pb[3], s_pw[30], s_pbo[10];

    if (threadIdx.x < 6) {                 // parallel trig preamble (MUFU)
        float th = 0.5f * q_params[3 + threadIdx.x];
        s_ts[threadIdx.x] = __sinf(th);
        s_tc[threadIdx.x] = __cosf(th);
    }
    if (threadIdx.x < 3)  s_pb[threadIdx.x]  = pre_b[threadIdx.x];
    if (threadIdx.x < 30) s_pw[threadIdx.x]  = post_W[threadIdx.x];
    if (threadIdx.x < 10) s_pbo[threadIdx.x] = post_b[threadIdx.x];
    __syncthreads();

    const int lane = threadIdx.x & 31;
    const int wib  = threadIdx.x >> 5;
    const int warp = blockIdx.x * WPB + wib;
    const int base = warp * SPW;
    if (base >= B) return;

    // Weights in registers: lane owns float4 chunks {32i + lane}, i=0..3.
    float4 wa[4], wb[4], wc[4];
    #pragma unroll
    for (int i = 0; i < 4; i++) {
        wa[i] = ((const float4*)(pre_W           ))[i * 32 + lane];
        wb[i] = ((const float4*)(pre_W +     FDIM))[i * 32 + lane];
        wc[i] = ((const float4*)(pre_W + 2 * FDIM))[i * 32 + lane];
    }

    const unsigned sbase = smem_u32(&s_x[wib][0][0]);

    // -------- prologue: fill DEPTH-1 stages ----------------------------------
    #pragma unroll
    for (int p = 0; p < DEPTH - 1; p++) {
        int r = base + p;
        if (r >= B) r = B - 1;
        cp_row(sbase + p * ROWB, x + (size_t)r * FDIM, lane);
        asm volatile("cp.async.commit_group;" ::: "memory");
    }

    // -------- steady state ---------------------------------------------------
    #pragma unroll 1
    for (int j = 0; j < SPW; j++) {
        __syncwarp();                      // stage (j-1)%DEPTH reads done before overwrite
        int jn = j + DEPTH - 1;
        if (jn < SPW) {
            int r = base + jn;
            if (r >= B) r = B - 1;
            cp_row(sbase + (jn % DEPTH) * ROWB, x + (size_t)r * FDIM, lane);
        }
        asm volatile("cp.async.commit_group;" ::: "memory");
        asm volatile("cp.async.wait_group %0;" :: "n"(DEPTH - 1) : "memory");
        __syncwarp();

        const float4* xs = (const float4*)&s_x[wib][j % DEPTH][0];
        float d0 = 0.f, d1 = 0.f, d2 = 0.f;
        #pragma unroll
        for (int i = 0; i < 4; i++) {
            float4 v = xs[i * 32 + lane];
            d0 += dot4(v, wa[i]);
            d1 += dot4(v, wb[i]);
            d2 += dot4(v, wc[i]);
        }
        #pragma unroll
        for (int off = 16; off; off >>= 1) {
            d0 += __shfl_xor_sync(0xffffffffu, d0, off);
            d1 += __shfl_xor_sync(0xffffffffu, d1, off);
            d2 += __shfl_xor_sync(0xffffffffu, d2, off);
        }
        if (lane < 3)
            s_md[wib][j][lane] = (lane == 0) ? d0 : (lane == 1) ? d1 : d2;
    }
    __syncwarp();

    // -------- epilogue: one sample per lane ----------------------------------
    int row = base + lane;
    if (row >= B) return;

    float h0 = fast_tanh(s_md[wib][lane][0] + s_pb[0]) * (PI_F * 0.25f);
    float h1 = fast_tanh(s_md[wib][lane][1] + s_pb[1]) * (PI_F * 0.25f);
    float h2 = fast_tanh(s_md[wib][lane][2] + s_pb[2]) * (PI_F * 0.25f);

    float st[8];
    const float inv8 = 0.3535533905932738f;    // amplitudes after H layer
    #pragma unroll
    for (int i = 0; i < 8; i++) st[i] = inv8;

    float ec, es;
    es = __sinf(h0); ec = __cosf(h0);          // encoding RY qubit 0 (stride 4)
    #pragma unroll
    for (int i = 0; i < 4; i++) {
        float a0 = st[i], a1 = st[i + 4];
        st[i]     = ec * a0 - es * a1;
        st[i + 4] = es * a0 + ec * a1;
    }
    es = __sinf(h1); ec = __cosf(h1);          // qubit 1 (stride 2)
    #pragma unroll
    for (int g = 0; g < 2; g++)
        #pragma unroll
        for (int i = 0; i < 2; i++) {
            int i0 = g * 4 + i;
            float a0 = st[i0], a1 = st[i0 + 2];
            st[i0]     = ec * a0 - es * a1;
            st[i0 + 2] = es * a0 + ec * a1;
        }
    es = __sinf(h2); ec = __cosf(h2);          // qubit 2 (stride 1)
    #pragma unroll
    for (int i0 = 0; i0 < 8; i0 += 2) {
        float a0 = st[i0], a1 = st[i0 + 1];
        st[i0]     = ec * a0 - es * a1;
        st[i0 + 1] = es * a0 + ec * a1;
    }

    #pragma unroll
    for (int k = 0; k < 2; k++) {
        float t;
        // CNOT01: swap (4,6),(5,7); CNOT12: swap (2,3),(6,7)
        t = st[4]; st[4] = st[6]; st[6] = t;
        t = st[5]; st[5] = st[7]; st[7] = t;
        t = st[2]; st[2] = st[3]; st[3] = t;
        t = st[6]; st[6] = st[7]; st[7] = t;

        float c0 = s_tc[k * 3 + 0], sg0 = s_ts[k * 3 + 0];
        float c1 = s_tc[k * 3 + 1], sg1 = s_ts[k * 3 + 1];
        float c2 = s_tc[k * 3 + 2], sg2 = s_ts[k * 3 + 2];
        #pragma unroll
        for (int i = 0; i < 4; i++) {
            float a0 = st[i], a1 = st[i + 4];
            st[i]     = c0 * a0 - sg0 * a1;
            st[i + 4] = sg0 * a0 + c0 * a1;
        }
        #pragma unroll
        for (int g = 0; g < 2; g++)
            #pragma unroll
            for (int i = 0; i < 2; i++) {
                int i0 = g * 4 + i;
                float a0 = st[i0], a1 = st[i0 + 2];
                st[i0]     = c1 * a0 - sg1 * a1;
                st[i0 + 2] = sg1 * a0 + c1 * a1;
            }
        #pragma unroll
        for (int i0 = 0; i0 < 8; i0 += 2) {
            float a0 = st[i0], a1 = st[i0 + 1];
            st[i0]     = c2 * a0 - sg2 * a1;
            st[i0 + 1] = sg2 * a0 + c2 * a1;
        }
    }

    float p[8];
    #pragma unroll
    for (int i = 0; i < 8; i++) p[i] = st[i] * st[i];
    float z0 = (p[0] + p[1] + p[2] + p[3]) - (p[4] + p[5] + p[6] + p[7]);
    float z1 = (p[0] + p[1] + p[4] + p[5]) - (p[2] + p[3] + p[6] + p[7]);
    float z2 = (p[0] + p[2] + p[4] + p[6]) - (p[1] + p[3] + p[5] + p[7]);

    float2* op = (float2*)(out + (size_t)row * NOUT);
    #pragma unroll
    for (int k = 0; k < 5; k++) {
        float2 w;
        w.x = z0 * s_pw[(2*k)   * 3 + 0] + z1 * s_pw[(2*k)   * 3 + 1]
            + z2 * s_pw[(2*k)   * 3 + 2] + s_pbo[2*k];
        w.y = z0 * s_pw[(2*k+1) * 3 + 0] + z1 * s_pw[(2*k+1) * 3 + 1]
            + z2 * s_pw[(2*k+1) * 3 + 2] + s_pbo[2*k+1];
        op[k] = w;
    }
}

extern "C" void kernel_launch(void* const* d_in, const int* in_sizes, int n_in,
                              void* d_out, int out_size) {
    const float* x      = (const float*)d_in[0];
    const float* pre_W  = (const float*)d_in[1];
    const float* pre_b  = (const float*)d_in[2];
    const float* q_par  = (const float*)d_in[3];
    const float* post_W = (const float*)d_in[4];
    const float* post_b = (const float*)d_in[5];
    float* out = (float*)d_out;

    int B = in_sizes[0] / FDIM;

    int warps_needed = (B + SPW - 1) / SPW;              // 2048 for B=65536
    int blocks       = (warps_needed + WPB - 1) / WPB;   // 512 blocks of 128
    qnet_fused_kernel<<<blocks, 128>>>(x, pre_W, pre_b, q_par,
                                       post_W, post_b, out, B);
}